// round 8
// baseline (speedup 1.0000x reference)
#include <cuda_runtime.h>
#include <cstdint>

#define SRC_LEN 512
#define BATCH   64
#define HIDDEN  1024
#define EMBED   1024
#define NBLK    128          // scan CTAs = 32 j-tiles x 4 b-tiles

// Scratch (static __device__ arrays: allowed, no runtime allocation)
__device__ float    g_xproj[SRC_LEN * HIDDEN * BATCH];   // [t][j][b]
__device__ float    g_h[2][HIDDEN * BATCH];              // ping-pong, [k][b]
__device__ unsigned g_bar;

typedef unsigned long long ull;

__device__ __forceinline__ ull pk2(float x, float y) {
    ull r; asm("mov.b64 %0, {%1, %2};" : "=l"(r) : "f"(x), "f"(y)); return r;
}
__device__ __forceinline__ void upk2(ull p, float& x, float& y) {
    asm("mov.b64 {%0, %1}, %2;" : "=f"(x), "=f"(y) : "l"(p));
}
__device__ __forceinline__ ull ffma2(ull a, ull b, ull c) {
    ull d; asm("fma.rn.f32x2 %0, %1, %2, %3;" : "=l"(d) : "l"(a), "l"(b), "l"(c)); return d;
}

// ---------------------------------------------------------------------------
__global__ void init_kernel() {
    unsigned i = blockIdx.x * blockDim.x + threadIdx.x;
    if (i == 0) g_bar = 0u;
    if (i < HIDDEN * BATCH) g_h[0][i] = 0.0f;
}

// ncu-steering no-ops: two probes shift `-s 5 -c 1` onto xproj this round.
__global__ void probe_kernel() { }

// ---------------------------------------------------------------------------
// Stage 1 v3: x_proj[t][j][b] = sum_e emb[src[b,t]][e] * Wxh[j][e] + bxh[j]
// Tile 64(b) x 128(j) x 16(k), 128 threads, 8b x 8j micro-tile.
// A in natural [b][k] (pad 20) -> 8 broadcast LDS.32 per kk.
// B transposed [k][j]          -> 2 LDS.128 j-quads per kk (bandwidth-minimal).
// Per warp/kk: ~12 crossbar phases vs 32 FFMA2 -> fma-pipe bound.
// ---------------------------------------------------------------------------
__global__ __launch_bounds__(128, 4) void xproj_kernel(
    const int*   __restrict__ src,
    const float* __restrict__ emb,
    const float* __restrict__ Wxh,
    const float* __restrict__ bxh)
{
    __shared__ __align__(16) float Asm[2][64][20];    // [b][k], pad 20
    __shared__ __align__(16) float Bsm[2][16][128];   // [k][j]

    const int jt  = blockIdx.x;          // 0..7
    const int t   = blockIdx.y;          // 0..511
    const int tid = threadIdx.x;

    // loaders: A -> thread owns (row a_r, k-octet a_h); B -> thread owns row j=tid
    const int a_r = tid >> 1, a_h = tid & 1;
    const float* arow = emb + (size_t)__ldg(src + a_r * SRC_LEN + t) * EMBED + a_h * 8;
    const float* brow = Wxh + (size_t)(jt * 128 + tid) * EMBED;

    // micro-tile: 8 rows (b) x 8 cols (j)
    const int b0 = (tid >> 4) * 8;
    const int j0 = (tid & 15) * 8;

    ull acc[8][4];
#pragma unroll
    for (int i = 0; i < 8; ++i) { acc[i][0]=0; acc[i][1]=0; acc[i][2]=0; acc[i][3]=0; }

    // prologue: slice 0 -> regs -> smem[0]
    float4 a0 = *(const float4*)(arow);
    float4 a1 = *(const float4*)(arow + 4);
    float4 w0 = *(const float4*)(brow);
    float4 w1 = *(const float4*)(brow + 4);
    float4 w2 = *(const float4*)(brow + 8);
    float4 w3 = *(const float4*)(brow + 12);
    *(float4*)&Asm[0][a_r][a_h*8]     = a0;
    *(float4*)&Asm[0][a_r][a_h*8 + 4] = a1;
    Bsm[0][ 0][tid]=w0.x; Bsm[0][ 1][tid]=w0.y; Bsm[0][ 2][tid]=w0.z; Bsm[0][ 3][tid]=w0.w;
    Bsm[0][ 4][tid]=w1.x; Bsm[0][ 5][tid]=w1.y; Bsm[0][ 6][tid]=w1.z; Bsm[0][ 7][tid]=w1.w;
    Bsm[0][ 8][tid]=w2.x; Bsm[0][ 9][tid]=w2.y; Bsm[0][10][tid]=w2.z; Bsm[0][11][tid]=w2.w;
    Bsm[0][12][tid]=w3.x; Bsm[0][13][tid]=w3.y; Bsm[0][14][tid]=w3.z; Bsm[0][15][tid]=w3.w;

    const int NT = EMBED / 16;   // 64
    for (int i = 0; i < NT; ++i) {
        __syncthreads();
        const int cur = i & 1;
        if (i + 1 < NT) {
            const int e0 = (i + 1) * 16;
            a0 = *(const float4*)(arow + e0);
            a1 = *(const float4*)(arow + e0 + 4);
            w0 = *(const float4*)(brow + e0);
            w1 = *(const float4*)(brow + e0 + 4);
            w2 = *(const float4*)(brow + e0 + 8);
            w3 = *(const float4*)(brow + e0 + 12);
        }
#pragma unroll
        for (int kk = 0; kk < 16; ++kk) {
            float a[8];
#pragma unroll
            for (int q = 0; q < 8; ++q) a[q] = Asm[cur][b0 + q][kk];
            ulonglong2 bA = *(const ulonglong2*)&Bsm[cur][kk][j0];
            ulonglong2 bB = *(const ulonglong2*)&Bsm[cur][kk][j0 + 4];
#pragma unroll
            for (int q = 0; q < 8; ++q) {
                ull p = pk2(a[q], a[q]);
                acc[q][0] = ffma2(p, bA.x, acc[q][0]);
                acc[q][1] = ffma2(p, bA.y, acc[q][1]);
                acc[q][2] = ffma2(p, bB.x, acc[q][2]);
                acc[q][3] = ffma2(p, bB.y, acc[q][3]);
            }
        }
        if (i + 1 < NT) {
            const int nxt = cur ^ 1;
            *(float4*)&Asm[nxt][a_r][a_h*8]     = a0;
            *(float4*)&Asm[nxt][a_r][a_h*8 + 4] = a1;
            Bsm[nxt][ 0][tid]=w0.x; Bsm[nxt][ 1][tid]=w0.y; Bsm[nxt][ 2][tid]=w0.z; Bsm[nxt][ 3][tid]=w0.w;
            Bsm[nxt][ 4][tid]=w1.x; Bsm[nxt][ 5][tid]=w1.y; Bsm[nxt][ 6][tid]=w1.z; Bsm[nxt][ 7][tid]=w1.w;
            Bsm[nxt][ 8][tid]=w2.x; Bsm[nxt][ 9][tid]=w2.y; Bsm[nxt][10][tid]=w2.z; Bsm[nxt][11][tid]=w2.w;
            Bsm[nxt][12][tid]=w3.x; Bsm[nxt][13][tid]=w3.y; Bsm[nxt][14][tid]=w3.z; Bsm[nxt][15][tid]=w3.w;
        }
    }

    // epilogue: unpack, add bias, write [t][j][b] as 2 float4 along b per j
    float cc[8][8];                      // [b][j]
#pragma unroll
    for (int q = 0; q < 8; ++q) {
        upk2(acc[q][0], cc[q][0], cc[q][1]);
        upk2(acc[q][1], cc[q][2], cc[q][3]);
        upk2(acc[q][2], cc[q][4], cc[q][5]);
        upk2(acc[q][3], cc[q][6], cc[q][7]);
    }
    float* obase = g_xproj + (size_t)t * (HIDDEN * BATCH) + b0;
#pragma unroll
    for (int jj = 0; jj < 8; ++jj) {
        const int j = jt * 128 + j0 + jj;
        const float bj = __ldg(bxh + j);
        float4 v0 = make_float4(cc[0][jj]+bj, cc[1][jj]+bj, cc[2][jj]+bj, cc[3][jj]+bj);
        float4 v1 = make_float4(cc[4][jj]+bj, cc[5][jj]+bj, cc[6][jj]+bj, cc[7][jj]+bj);
        *(float4*)(obase + (size_t)j * BATCH)     = v0;
        *(float4*)(obase + (size_t)j * BATCH + 4) = v1;
    }
}

// ---------------------------------------------------------------------------
// Stage 2: persistent RNN scan (UNCHANGED from R7 — isolates xproj delta).
// ---------------------------------------------------------------------------
__global__ __launch_bounds__(512, 1) void rnn_scan_kernel(
    const float* __restrict__ Whh, float* __restrict__ out)
{
    extern __shared__ __align__(16) float sm[];
    float* Wt  = sm;              // [1024][32]  131072 B, plain [k][j]
    float* hst = sm + 32768;      // [1024][16]  65536 B, plain [k][b]
    float* red = hst;             // aliased: [16 kg][16 b(x36)]

    const int tid = threadIdx.x;
    const int jt  = blockIdx.x >> 2;    // 0..31
    const int bt  = blockIdx.x & 3;     // 0..3

    // ---- load W rows jt*32..+31, transposed to [k][32j] via 32x33 stage ----
    {
        const int kk = tid & 31, jh = tid >> 5;     // read coords (jh 0..15)
        const int j2 = tid & 31, kh = tid >> 5;     // write coords
        for (int k0 = 0; k0 < HIDDEN; k0 += 32) {
            red[jh * 33 + kk]        = __ldg(Whh + (size_t)(jt*32 + jh     ) * HIDDEN + k0 + kk);
            red[(jh + 16) * 33 + kk] = __ldg(Whh + (size_t)(jt*32 + jh + 16) * HIDDEN + k0 + kk);
            __syncthreads();
            Wt[(k0 + kh     ) * 32 + j2] = red[j2 * 33 + kh];
            Wt[(k0 + kh + 16) * 32 + j2] = red[j2 * 33 + kh + 16];
            __syncthreads();
        }
    }

    const int kg = tid >> 5;            // warp id = k-slice (64 k)
    const int jg = tid & 7;             // j quad 0..7
    const int bg = (tid >> 3) & 3;      // b quad 0..3
    const int rb = tid & 15;            // reduce coords
    const int rj = tid >> 4;            // 0..31

    const float* wbase = Wt  + (kg * 64) * 32 + jg * 4;
    const float* hbase = hst + (kg * 64) * 16 + bg * 4;
    float*       rpill = red + kg * 576 + (bg * 4) * 36 + jg * 4;
    const float* xp    = g_xproj + (size_t)(jt * 32 + rj) * BATCH + bt * 16 + rb;
    const int    houto = (jt * 32 + rj) * BATCH + bt * 16 + rb;

    unsigned expected = 0;
    int   cur   = 0;
    float lastv = 0.0f;

    for (int t = 0; t < SRC_LEN; ++t) {
        const float xv = __ldcg(xp + (size_t)t * (HIDDEN * BATCH));

        // ---- stage h slice [1024 k][16 b] (coalesced LDG.128 -> STS.128) ----
        const float* gh = g_h[cur] + bt * 16;
#pragma unroll
        for (int i = 0; i < 8; ++i) {
            const int idx = tid + i * 512;
            const int k = idx >> 2, bq = idx & 3;
            float4 v = __ldcg((const float4*)(gh + k * BATCH + bq * 4));
            *(float4*)&hst[k * 16 + bq * 4] = v;
        }
        __syncthreads();

        // ---- accumulate: 64 k x (4b x 4j), 8 FFMA2 per k ----
        ull a00=0,a01=0, a10=0,a11=0, a20=0,a21=0, a30=0,a31=0;
#pragma unroll 8
        for (int k = 0; k < 64; ++k) {
            float4     h4 = *(const float4*)    (hbase + k * 16);
            ulonglong2 w2 = *(const ulonglong2*)(wbase + k * 32);
            ull p;
            p = pk2(h4.x, h4.x); a00=ffma2(p,w2.x,a00); a01=ffma2(p,w2.y,a01);
            p = pk2(h4.y, h4.y); a10=ffma2(p,w2.x,a10); a11=ffma2(p,w2.y,a11);
            p = pk2(h4.z, h4.z); a20=ffma2(p,w2.x,a20); a21=ffma2(p,w2.y,a21);
            p = pk2(h4.w, h4.w); a30=ffma2(p,w2.x,a30); a31=ffma2(p,w2.y,a31);
        }
        __syncthreads();     // hst reads done before red (aliased) is written

        // ---- spill partials: red[kg][b][j], stride 36 ----
        *(ulonglong2*)(rpill         ) = make_ulonglong2(a00, a01);
        *(ulonglong2*)(rpill + 1 * 36) = make_ulonglong2(a10, a11);
        *(ulonglong2*)(rpill + 2 * 36) = make_ulonglong2(a20, a21);
        *(ulonglong2*)(rpill + 3 * 36) = make_ulonglong2(a30, a31);
        __syncthreads();

        // ---- reduce 16 k-slices, tanh, store h ----
        float s = xv;
#pragma unroll
        for (int q = 0; q < 16; ++q) s += red[q * 576 + rb * 36 + rj];
        lastv = tanhf(s);
        __stcg(g_h[cur ^ 1] + houto, lastv);

        // ---- grid-wide barrier (monotonic counter, reset per launch) ----
        expected += NBLK;
        __threadfence();
        __syncthreads();
        if (tid == 0) {
            atomicAdd(&g_bar, 1u);
            while (*(volatile unsigned*)&g_bar < expected) { }
        }
        __syncthreads();
        cur ^= 1;
    }
    out[(size_t)(bt * 16 + rb) * HIDDEN + jt * 32 + rj] = lastv;
}

// ---------------------------------------------------------------------------
extern "C" void kernel_launch(void* const* d_in, const int* in_sizes, int n_in,
                              void* d_out, int out_size)
{
    const int*   src = (const int*)  d_in[0];
    const float* emb = (const float*)d_in[1];
    const float* Wxh = (const float*)d_in[2];
    const float* bxh = (const float*)d_in[3];
    const float* Whh = (const float*)d_in[4];
    float* out = (float*)d_out;

    static int smem_set = 0;
    const int scan_smem = (32768 + 16384) * sizeof(float);   // 196608 B
    if (!smem_set) {
        cudaFuncSetAttribute(rnn_scan_kernel,
                             cudaFuncAttributeMaxDynamicSharedMemorySize, scan_smem);
        smem_set = 1;
    }

    init_kernel<<<256, 256>>>();
    probe_kernel<<<1, 32>>>();       // ncu alignment probes: capture -> xproj
    probe_kernel<<<1, 32>>>();
    xproj_kernel<<<dim3(8, SRC_LEN), 128>>>(src, emb, Wxh, bxh);
    rnn_scan_kernel<<<NBLK, 512, scan_smem>>>(Whh, out);
}

// round 11
// speedup vs baseline: 1.3824x; 1.3824x over previous
#include <cuda_runtime.h>
#include <cuda_bf16.h>
#include <cstdint>

#define SRC_LEN 512
#define BATCH   64
#define HIDDEN  1024
#define EMBED   1024
#define NBLK    128          // scan CTAs = 32 j-tiles x 4 b-tiles

// Scratch (static __device__ arrays: allowed, no runtime allocation)
__device__ float    g_xproj[SRC_LEN * HIDDEN * BATCH];   // [t][j][b]
__device__ float    g_h[2][HIDDEN * BATCH];              // ping-pong, [k][b]
__device__ unsigned g_bar;

typedef unsigned long long ull;

__device__ __forceinline__ ull pk2(float x, float y) {
    ull r; asm("mov.b64 %0, {%1, %2};" : "=l"(r) : "f"(x), "f"(y)); return r;
}
__device__ __forceinline__ ull ffma2(ull a, ull b, ull c) {
    ull d; asm("fma.rn.f32x2 %0, %1, %2, %3;" : "=l"(d) : "l"(a), "l"(b), "l"(c)); return d;
}
__device__ __forceinline__ uint32_t smem_u32(const void* p) {
    uint32_t a;
    asm("{ .reg .u64 t; cvta.to.shared.u64 t, %1; cvt.u32.u64 %0, t; }" : "=r"(a) : "l"(p));
    return a;
}

// ---- warp-level bf16 MMA primitives (sm_80+, safe on bare sm_103) ---------
#define LDSM_X4(r, a) \
    asm volatile("ldmatrix.sync.aligned.m8n8.x4.shared.b16 {%0,%1,%2,%3}, [%4];" \
        : "=r"((r)[0]), "=r"((r)[1]), "=r"((r)[2]), "=r"((r)[3]) : "r"(a))

__device__ __forceinline__ void mma16816(float* c, const unsigned* a,
                                         unsigned b0, unsigned b1) {
    asm volatile(
        "mma.sync.aligned.m16n8k16.row.col.f32.bf16.bf16.f32 "
        "{%0,%1,%2,%3}, {%4,%5,%6,%7}, {%8,%9}, {%0,%1,%2,%3};"
        : "+f"(c[0]), "+f"(c[1]), "+f"(c[2]), "+f"(c[3])
        : "r"(a[0]), "r"(a[1]), "r"(a[2]), "r"(a[3]), "r"(b0), "r"(b1));
}

__device__ __forceinline__ unsigned bf2u(__nv_bfloat162 h) {
    unsigned u; __builtin_memcpy(&u, &h, 4); return u;
}
// 8 fp32 -> 8 bf16 hi + 8 bf16 lo (split)
__device__ __forceinline__ void cvt8(float4 a, float4 b, uint4& hi, uint4& lo) {
    __nv_bfloat162 h0 = __float22bfloat162_rn(make_float2(a.x, a.y));
    __nv_bfloat162 h1 = __float22bfloat162_rn(make_float2(a.z, a.w));
    __nv_bfloat162 h2 = __float22bfloat162_rn(make_float2(b.x, b.y));
    __nv_bfloat162 h3 = __float22bfloat162_rn(make_float2(b.z, b.w));
    float2 f0 = __bfloat1622float2(h0), f1 = __bfloat1622float2(h1);
    float2 f2 = __bfloat1622float2(h2), f3 = __bfloat1622float2(h3);
    __nv_bfloat162 l0 = __float22bfloat162_rn(make_float2(a.x - f0.x, a.y - f0.y));
    __nv_bfloat162 l1 = __float22bfloat162_rn(make_float2(a.z - f1.x, a.w - f1.y));
    __nv_bfloat162 l2 = __float22bfloat162_rn(make_float2(b.x - f2.x, b.y - f2.y));
    __nv_bfloat162 l3 = __float22bfloat162_rn(make_float2(b.z - f3.x, b.w - f3.y));
    hi = make_uint4(bf2u(h0), bf2u(h1), bf2u(h2), bf2u(h3));
    lo = make_uint4(bf2u(l0), bf2u(l1), bf2u(l2), bf2u(l3));
}

// ---------------------------------------------------------------------------
__global__ void init_kernel() {
    unsigned i = blockIdx.x * blockDim.x + threadIdx.x;
    if (i == 0) g_bar = 0u;
    if (i < HIDDEN * BATCH) g_h[0][i] = 0.0f;
}
// ncu-steering no-ops: capture (4th launch) lands on xproj.
__global__ void probe_kernel() { }

// ---------------------------------------------------------------------------
// Stage 1 v5 (warp MMA): x_proj = gather(emb,src) @ Wxh^T + bxh, bf16-split.
// CTA 256thr/8warps: M=128 rows (2t x 64b), N=128 j, K chunks of 32.
// SMEM rows padded to 40 bf16 (80B = 5x16B): ldmatrix-aligned, conflict-free.
// D = Ah*Bh + Ah*Bl + Al*Bh  (lo*lo dropped, ~2^-16).
// B stored [n][k] k-contiguous -> NON-trans ldmatrix IS the col-major B frag.
// ---------------------------------------------------------------------------
#define XROW 40            // bf16 per SMEM row (32 data + 8 pad)
#define XROWB 80           // bytes

__global__ __launch_bounds__(256, 2) void xproj_kernel(
    const int*   __restrict__ src,
    const float* __restrict__ emb,
    const float* __restrict__ Wxh,
    const float* __restrict__ bxh)
{
    __shared__ __align__(16) unsigned char smAH[128 * XROWB];
    __shared__ __align__(16) unsigned char smAL[128 * XROWB];
    __shared__ __align__(16) unsigned char smBH[128 * XROWB];
    __shared__ __align__(16) unsigned char smBL[128 * XROWB];

    const int tid = threadIdx.x;
    const int j0 = blockIdx.x * 128;       // j tile
    const int t0 = blockIdx.y * 2;         // 2 timesteps

    // ---- staging roles: thread owns row ra (A and B), k-half kh ----
    const int ra = tid >> 1;               // 0..127
    const int kh = (tid & 1) * 16;         // 0 / 16 within 32-k chunk
    const int bb = ra & 63, tl0 = ra >> 6;
    const int er = __ldg(src + bb * SRC_LEN + t0 + tl0);
    const float* arow = emb + (size_t)er * EMBED + kh;
    const float* brow = Wxh + (size_t)(j0 + ra) * EMBED + kh;
    unsigned char* pAH = smAH + ra * XROWB + kh * 2;
    unsigned char* pAL = smAL + ra * XROWB + kh * 2;
    unsigned char* pBH = smBH + ra * XROWB + kh * 2;
    unsigned char* pBL = smBL + ra * XROWB + kh * 2;

    // ---- ldmatrix per-lane addresses ----
    const int l = tid & 31, w = tid >> 5;
    const int rowA = 16 * w + (l & 7) + (l & 8);
    const int kA   = (l >> 4) * 8;
    const uint32_t aAH = smem_u32(smAH) + rowA * XROWB + kA * 2;
    const uint32_t aAL = smem_u32(smAL) + rowA * XROWB + kA * 2;
    const int rowB = (l & 7) + ((l >= 16) ? 8 : 0);
    const int kB   = (l & 8) ? 8 : 0;
    const uint32_t aBH = smem_u32(smBH) + rowB * XROWB + kB * 2;
    const uint32_t aBL = smem_u32(smBL) + rowB * XROWB + kB * 2;

    float acc[16][4];
#pragma unroll
    for (int n = 0; n < 16; ++n) { acc[n][0]=0.f; acc[n][1]=0.f; acc[n][2]=0.f; acc[n][3]=0.f; }

    for (int c = 0; c < EMBED / 32; ++c) {
        const int k0 = c * 32;
        float4 va0 = __ldg((const float4*)(arow + k0));
        float4 va1 = __ldg((const float4*)(arow + k0 + 4));
        float4 va2 = __ldg((const float4*)(arow + k0 + 8));
        float4 va3 = __ldg((const float4*)(arow + k0 + 12));
        float4 vb0 = __ldg((const float4*)(brow + k0));
        float4 vb1 = __ldg((const float4*)(brow + k0 + 4));
        float4 vb2 = __ldg((const float4*)(brow + k0 + 8));
        float4 vb3 = __ldg((const float4*)(brow + k0 + 12));
        __syncthreads();                       // prev compute done
        uint4 h, lo;
        cvt8(va0, va1, h, lo); *(uint4*)pAH = h; *(uint4*)pAL = lo;
        cvt8(va2, va3, h, lo); *(uint4*)(pAH + 16) = h; *(uint4*)(pAL + 16) = lo;
        cvt8(vb0, vb1, h, lo); *(uint4*)pBH = h; *(uint4*)pBL = lo;
        cvt8(vb2, vb3, h, lo); *(uint4*)(pBH + 16) = h; *(uint4*)(pBL + 16) = lo;
        __syncthreads();                       // stage visible

#pragma unroll
        for (int kk = 0; kk < 2; ++kk) {
            unsigned ah[4], al[4];
            LDSM_X4(ah, aAH + kk * 32);
            LDSM_X4(al, aAL + kk * 32);
#pragma unroll
            for (int g = 0; g < 8; ++g) {
                unsigned bh[4], bl[4];
                LDSM_X4(bh, aBH + g * 16 * XROWB + kk * 32);
                LDSM_X4(bl, aBL + g * 16 * XROWB + kk * 32);
                mma16816(acc[2*g],   ah, bh[0], bh[1]);
                mma16816(acc[2*g],   ah, bl[0], bl[1]);
                mma16816(acc[2*g],   al, bh[0], bh[1]);
                mma16816(acc[2*g+1], ah, bh[2], bh[3]);
                mma16816(acc[2*g+1], ah, bl[2], bl[3]);
                mma16816(acc[2*g+1], al, bh[2], bh[3]);
            }
        }
    }

    // ---- epilogue: D(lane) rows r0=16w+(l>>2), r1=r0+8; cols j0+8nt+(l&3)*2
    const int r0 = 16 * w + (l >> 2);
    const int tl = r0 >> 6, b0 = r0 & 63;          // r1 = r0+8 -> same tl, b0+8
    float* ob = g_xproj + (size_t)(t0 + tl) * (HIDDEN * BATCH) + b0;
#pragma unroll
    for (int nt = 0; nt < 16; ++nt) {
        const int j = j0 + nt * 8 + (l & 3) * 2;
        const float bj0 = __ldg(bxh + j), bj1 = __ldg(bxh + j + 1);
        ob[(size_t)j       * BATCH]     = acc[nt][0] + bj0;
        ob[(size_t)(j + 1) * BATCH]     = acc[nt][1] + bj1;
        ob[(size_t)j       * BATCH + 8] = acc[nt][2] + bj0;
        ob[(size_t)(j + 1) * BATCH + 8] = acc[nt][3] + bj1;
    }
}

// ---------------------------------------------------------------------------
// Stage 2: persistent RNN scan (UNCHANGED from R7 — isolates xproj delta).
// ---------------------------------------------------------------------------
__global__ __launch_bounds__(512, 1) void rnn_scan_kernel(
    const float* __restrict__ Whh, float* __restrict__ out)
{
    extern __shared__ unsigned char dynsm[];
    float* sm  = (float*)dynsm;
    float* Wt  = sm;              // [1024][32]  131072 B, plain [k][j]
    float* hst = sm + 32768;      // [1024][16]  65536 B, plain [k][b]
    float* red = hst;             // aliased: [16 kg][16 b(x36)]

    const int tid = threadIdx.x;
    const int jt  = blockIdx.x >> 2;    // 0..31
    const int bt  = blockIdx.x & 3;     // 0..3

    // ---- load W rows jt*32..+31, transposed to [k][32j] via 32x33 stage ----
    {
        const int kk = tid & 31, jh = tid >> 5;     // read coords (jh 0..15)
        const int j2 = tid & 31, kh2 = tid >> 5;    // write coords
        for (int k0 = 0; k0 < HIDDEN; k0 += 32) {
            red[jh * 33 + kk]        = __ldg(Whh + (size_t)(jt*32 + jh     ) * HIDDEN + k0 + kk);
            red[(jh + 16) * 33 + kk] = __ldg(Whh + (size_t)(jt*32 + jh + 16) * HIDDEN + k0 + kk);
            __syncthreads();
            Wt[(k0 + kh2     ) * 32 + j2] = red[j2 * 33 + kh2];
            Wt[(k0 + kh2 + 16) * 32 + j2] = red[j2 * 33 + kh2 + 16];
            __syncthreads();
        }
    }

    const int kg = tid >> 5;            // warp id = k-slice (64 k)
    const int jg = tid & 7;             // j quad 0..7
    const int bg = (tid >> 3) & 3;      // b quad 0..3
    const int rb = tid & 15;            // reduce coords
    const int rj = tid >> 4;            // 0..31

    const float* wbase = Wt  + (kg * 64) * 32 + jg * 4;
    const float* hbase = hst + (kg * 64) * 16 + bg * 4;
    float*       rpill = red + kg * 576 + (bg * 4) * 36 + jg * 4;
    const float* xp    = g_xproj + (size_t)(jt * 32 + rj) * BATCH + bt * 16 + rb;
    const int    houto = (jt * 32 + rj) * BATCH + bt * 16 + rb;

    unsigned expected = 0;
    int   cur   = 0;
    float lastv = 0.0f;

    for (int t = 0; t < SRC_LEN; ++t) {
        const float xv = __ldcg(xp + (size_t)t * (HIDDEN * BATCH));

        // ---- stage h slice [1024 k][16 b] (coalesced LDG.128 -> STS.128) ----
        const float* gh = g_h[cur] + bt * 16;
#pragma unroll
        for (int i = 0; i < 8; ++i) {
            const int idx = tid + i * 512;
            const int k = idx >> 2, bq = idx & 3;
            float4 v = __ldcg((const float4*)(gh + k * BATCH + bq * 4));
            *(float4*)&hst[k * 16 + bq * 4] = v;
        }
        __syncthreads();

        // ---- accumulate: 64 k x (4b x 4j), 8 FFMA2 per k ----
        ull a00=0,a01=0, a10=0,a11=0, a20=0,a21=0, a30=0,a31=0;
#pragma unroll 8
        for (int k = 0; k < 64; ++k) {
            float4     h4 = *(const float4*)    (hbase + k * 16);
            ulonglong2 w2 = *(const ulonglong2*)(wbase + k * 32);
            ull p;
            p = pk2(h4.x, h4.x); a00=ffma2(p,w2.x,a00); a01=ffma2(p,w2.y,a01);
            p = pk2(h4.y, h4.y); a10=ffma2(p,w2.x,a10); a11=ffma2(p,w2.y,a11);
            p = pk2(h4.z, h4.z); a20=ffma2(p,w2.x,a20); a21=ffma2(p,w2.y,a21);
            p = pk2(h4.w, h4.w); a30=ffma2(p,w2.x,a30); a31=ffma2(p,w2.y,a31);
        }
        __syncthreads();     // hst reads done before red (aliased) is written

        // ---- spill partials: red[kg][b][j], stride 36 ----
        *(ulonglong2*)(rpill         ) = make_ulonglong2(a00, a01);
        *(ulonglong2*)(rpill + 1 * 36) = make_ulonglong2(a10, a11);
        *(ulonglong2*)(rpill + 2 * 36) = make_ulonglong2(a20, a21);
        *(ulonglong2*)(rpill + 3 * 36) = make_ulonglong2(a30, a31);
        __syncthreads();

        // ---- reduce 16 k-slices, tanh, store h ----
        float s = xv;
#pragma unroll
        for (int q = 0; q < 16; ++q) s += red[q * 576 + rb * 36 + rj];
        lastv = tanhf(s);
        __stcg(g_h[cur ^ 1] + houto, lastv);

        // ---- grid-wide barrier (monotonic counter, reset per launch) ----
        expected += NBLK;
        __threadfence();
        __syncthreads();
        if (tid == 0) {
            atomicAdd(&g_bar, 1u);
            while (*(volatile unsigned*)&g_bar < expected) { }
        }
        __syncthreads();
        cur ^= 1;
    }
    out[(size_t)(bt * 16 + rb) * HIDDEN + jt * 32 + rj] = lastv;
}

// ---------------------------------------------------------------------------
extern "C" void kernel_launch(void* const* d_in, const int* in_sizes, int n_in,
                              void* d_out, int out_size)
{
    const int*   src = (const int*)  d_in[0];
    const float* emb = (const float*)d_in[1];
    const float* Wxh = (const float*)d_in[2];
    const float* bxh = (const float*)d_in[3];
    const float* Whh = (const float*)d_in[4];
    float* out = (float*)d_out;

    static int attr_set = 0;
    const int scan_smem = (32768 + 16384) * sizeof(float);   // 196608 B
    if (!attr_set) {
        cudaFuncSetAttribute(rnn_scan_kernel,
                             cudaFuncAttributeMaxDynamicSharedMemorySize, scan_smem);
        attr_set = 1;
    }

    init_kernel<<<256, 256>>>();
    probe_kernel<<<1, 32>>>();       // ncu alignment: capture -> xproj (warp MMA)
    probe_kernel<<<1, 32>>>();
    xproj_kernel<<<dim3(8, 256), 256>>>(src, emb, Wxh, bxh);
    rnn_scan_kernel<<<NBLK, 512, scan_smem>>>(Whh, out);
}

// round 12
// speedup vs baseline: 2.0626x; 1.4921x over previous
#include <cuda_runtime.h>
#include <cuda_bf16.h>
#include <cstdint>

#define SRC_LEN 512
#define BATCH   64
#define HIDDEN  1024
#define EMBED   1024
#define NBLK    128          // scan CTAs = 32 j-tiles x 4 b-tiles

// Scratch (static __device__ arrays: allowed, no runtime allocation)
__device__ float    g_xproj[SRC_LEN * BATCH * HIDDEN];   // [t][b][j]
__device__ float    g_h[2][BATCH * HIDDEN];              // ping-pong, [b][k]
__device__ unsigned g_bar;

__device__ __forceinline__ uint32_t smem_u32(const void* p) {
    uint32_t a;
    asm("{ .reg .u64 t; cvta.to.shared.u64 t, %1; cvt.u32.u64 %0, t; }" : "=r"(a) : "l"(p));
    return a;
}

// ---- warp-level bf16 MMA primitives (sm_80+, safe on bare sm_103) ---------
#define LDSM_X4(r, a) \
    asm volatile("ldmatrix.sync.aligned.m8n8.x4.shared.b16 {%0,%1,%2,%3}, [%4];" \
        : "=r"((r)[0]), "=r"((r)[1]), "=r"((r)[2]), "=r"((r)[3]) : "r"(a))

__device__ __forceinline__ void mma16816(float* c, const unsigned* a,
                                         unsigned b0, unsigned b1) {
    asm volatile(
        "mma.sync.aligned.m16n8k16.row.col.f32.bf16.bf16.f32 "
        "{%0,%1,%2,%3}, {%4,%5,%6,%7}, {%8,%9}, {%0,%1,%2,%3};"
        : "+f"(c[0]), "+f"(c[1]), "+f"(c[2]), "+f"(c[3])
        : "r"(a[0]), "r"(a[1]), "r"(a[2]), "r"(a[3]), "r"(b0), "r"(b1));
}

__device__ __forceinline__ unsigned bf2u(__nv_bfloat162 h) {
    unsigned u; __builtin_memcpy(&u, &h, 4); return u;
}
// 8 fp32 -> 8 bf16 hi + 8 bf16 lo (split)
__device__ __forceinline__ void cvt8(float4 a, float4 b, uint4& hi, uint4& lo) {
    __nv_bfloat162 h0 = __float22bfloat162_rn(make_float2(a.x, a.y));
    __nv_bfloat162 h1 = __float22bfloat162_rn(make_float2(a.z, a.w));
    __nv_bfloat162 h2 = __float22bfloat162_rn(make_float2(b.x, b.y));
    __nv_bfloat162 h3 = __float22bfloat162_rn(make_float2(b.z, b.w));
    float2 f0 = __bfloat1622float2(h0), f1 = __bfloat1622float2(h1);
    float2 f2 = __bfloat1622float2(h2), f3 = __bfloat1622float2(h3);
    __nv_bfloat162 l0 = __float22bfloat162_rn(make_float2(a.x - f0.x, a.y - f0.y));
    __nv_bfloat162 l1 = __float22bfloat162_rn(make_float2(a.z - f1.x, a.w - f1.y));
    __nv_bfloat162 l2 = __float22bfloat162_rn(make_float2(b.x - f2.x, b.y - f2.y));
    __nv_bfloat162 l3 = __float22bfloat162_rn(make_float2(b.z - f3.x, b.w - f3.y));
    hi = make_uint4(bf2u(h0), bf2u(h1), bf2u(h2), bf2u(h3));
    lo = make_uint4(bf2u(l0), bf2u(l1), bf2u(l2), bf2u(l3));
}
// 4 fp32 -> 4 bf16 hi + lo
__device__ __forceinline__ void cvt4(float4 a, uint2& hi, uint2& lo) {
    __nv_bfloat162 h0 = __float22bfloat162_rn(make_float2(a.x, a.y));
    __nv_bfloat162 h1 = __float22bfloat162_rn(make_float2(a.z, a.w));
    float2 f0 = __bfloat1622float2(h0), f1 = __bfloat1622float2(h1);
    __nv_bfloat162 l0 = __float22bfloat162_rn(make_float2(a.x - f0.x, a.y - f0.y));
    __nv_bfloat162 l1 = __float22bfloat162_rn(make_float2(a.z - f1.x, a.w - f1.y));
    hi = make_uint2(bf2u(h0), bf2u(h1));
    lo = make_uint2(bf2u(l0), bf2u(l1));
}

// ---------------------------------------------------------------------------
__global__ void init_kernel() {
    unsigned i = blockIdx.x * blockDim.x + threadIdx.x;
    if (i == 0) g_bar = 0u;
    if (i < HIDDEN * BATCH) g_h[0][i] = 0.0f;
}
// ncu-steering no-op: capture (4th launch) lands on the new scan kernel.
__global__ void probe_kernel() { }

// ---------------------------------------------------------------------------
// Stage 1 (warp MMA, unchanged math from R11 WIN): epilogue now [t][b][j].
// ---------------------------------------------------------------------------
#define XROWB 80           // bytes per SMEM row (32 data + 8 pad bf16)

__global__ __launch_bounds__(256, 2) void xproj_kernel(
    const int*   __restrict__ src,
    const float* __restrict__ emb,
    const float* __restrict__ Wxh,
    const float* __restrict__ bxh)
{
    __shared__ __align__(16) unsigned char smAH[128 * XROWB];
    __shared__ __align__(16) unsigned char smAL[128 * XROWB];
    __shared__ __align__(16) unsigned char smBH[128 * XROWB];
    __shared__ __align__(16) unsigned char smBL[128 * XROWB];

    const int tid = threadIdx.x;
    const int j0 = blockIdx.x * 128;
    const int t0 = blockIdx.y * 2;

    const int ra = tid >> 1;
    const int kh = (tid & 1) * 16;
    const int bb = ra & 63, tl0 = ra >> 6;
    const int er = __ldg(src + bb * SRC_LEN + t0 + tl0);
    const float* arow = emb + (size_t)er * EMBED + kh;
    const float* brow = Wxh + (size_t)(j0 + ra) * EMBED + kh;
    unsigned char* pAH = smAH + ra * XROWB + kh * 2;
    unsigned char* pAL = smAL + ra * XROWB + kh * 2;
    unsigned char* pBH = smBH + ra * XROWB + kh * 2;
    unsigned char* pBL = smBL + ra * XROWB + kh * 2;

    const int l = tid & 31, w = tid >> 5;
    const int rowA = 16 * w + (l & 7) + (l & 8);
    const int kA   = (l >> 4) * 8;
    const uint32_t aAH = smem_u32(smAH) + rowA * XROWB + kA * 2;
    const uint32_t aAL = smem_u32(smAL) + rowA * XROWB + kA * 2;
    const int rowB = (l & 7) + ((l >= 16) ? 8 : 0);
    const int kB   = (l & 8) ? 8 : 0;
    const uint32_t aBH = smem_u32(smBH) + rowB * XROWB + kB * 2;
    const uint32_t aBL = smem_u32(smBL) + rowB * XROWB + kB * 2;

    float acc[16][4];
#pragma unroll
    for (int n = 0; n < 16; ++n) { acc[n][0]=0.f; acc[n][1]=0.f; acc[n][2]=0.f; acc[n][3]=0.f; }

    for (int c = 0; c < EMBED / 32; ++c) {
        const int k0 = c * 32;
        float4 va0 = __ldg((const float4*)(arow + k0));
        float4 va1 = __ldg((const float4*)(arow + k0 + 4));
        float4 va2 = __ldg((const float4*)(arow + k0 + 8));
        float4 va3 = __ldg((const float4*)(arow + k0 + 12));
        float4 vb0 = __ldg((const float4*)(brow + k0));
        float4 vb1 = __ldg((const float4*)(brow + k0 + 4));
        float4 vb2 = __ldg((const float4*)(brow + k0 + 8));
        float4 vb3 = __ldg((const float4*)(brow + k0 + 12));
        __syncthreads();
        uint4 h, lo;
        cvt8(va0, va1, h, lo); *(uint4*)pAH = h; *(uint4*)pAL = lo;
        cvt8(va2, va3, h, lo); *(uint4*)(pAH + 16) = h; *(uint4*)(pAL + 16) = lo;
        cvt8(vb0, vb1, h, lo); *(uint4*)pBH = h; *(uint4*)pBL = lo;
        cvt8(vb2, vb3, h, lo); *(uint4*)(pBH + 16) = h; *(uint4*)(pBL + 16) = lo;
        __syncthreads();

#pragma unroll
        for (int kk = 0; kk < 2; ++kk) {
            unsigned ah[4], al[4];
            LDSM_X4(ah, aAH + kk * 32);
            LDSM_X4(al, aAL + kk * 32);
#pragma unroll
            for (int g = 0; g < 8; ++g) {
                unsigned bh[4], bl[4];
                LDSM_X4(bh, aBH + g * 16 * XROWB + kk * 32);
                LDSM_X4(bl, aBL + g * 16 * XROWB + kk * 32);
                mma16816(acc[2*g],   ah, bh[0], bh[1]);
                mma16816(acc[2*g],   ah, bl[0], bl[1]);
                mma16816(acc[2*g],   al, bh[0], bh[1]);
                mma16816(acc[2*g+1], ah, bh[2], bh[3]);
                mma16816(acc[2*g+1], ah, bl[2], bl[3]);
                mma16816(acc[2*g+1], al, bh[2], bh[3]);
            }
        }
    }

    // epilogue -> g_xproj[t][b][j], float2 stores (j even)
    const int r0 = 16 * w + (l >> 2);
    const int tl = r0 >> 6, b0 = r0 & 63;
    float* base0 = g_xproj + ((size_t)(t0 + tl) * BATCH + b0) * HIDDEN;
    float* base1 = g_xproj + ((size_t)(t0 + tl) * BATCH + b0 + 8) * HIDDEN;
#pragma unroll
    for (int nt = 0; nt < 16; ++nt) {
        const int j = j0 + nt * 8 + (l & 3) * 2;
        const float bj0 = __ldg(bxh + j), bj1 = __ldg(bxh + j + 1);
        *(float2*)(base0 + j) = make_float2(acc[nt][0] + bj0, acc[nt][1] + bj1);
        *(float2*)(base1 + j) = make_float2(acc[nt][2] + bj0, acc[nt][3] + bj1);
    }
}

// ---------------------------------------------------------------------------
// Stage 2 v3 (warp MMA): persistent scan, 128 CTAs (32 jt x 4 bt), 256 thr.
// W_hh bf16-split B-fragments preloaded into REGISTERS once (time-invariant).
// Per step: stage h (16x1024 fp32 -> bf16 hi/lo, XOR-16B swizzle), warp =
// K-slice 128: 16 LDSM + 96 HMMA; spill fp32 partials; 8-way reduce; tanh.
// ---------------------------------------------------------------------------
#define KROWB   2064        // bytes per 1024-bf16 row (+8 pad)
#define OFF_WH  0
#define OFF_WL  66048
#define OFF_AH  132096
#define OFF_AL  165120
#define OFF_RED 198144
#define SCAN_SMEM 218624

__global__ __launch_bounds__(256) void rnn_scan_kernel(
    const float* __restrict__ Whh, float* __restrict__ out)
{
    extern __shared__ __align__(16) unsigned char dynsm[];
    const uint32_t sbase = smem_u32(dynsm);
    float* red = (float*)(dynsm + OFF_RED);

    const int tid = threadIdx.x;
    const int l = tid & 31, w = tid >> 5;
    const int jt = blockIdx.x >> 2, bt = blockIdx.x & 3;

    // ---- W prologue: rows jt*32..+31 fp32 -> bf16 hi/lo SMEM [j][k] ----
    {
        const int r = tid >> 3, kq = tid & 7;
        const float* wr = Whh + (size_t)(jt * 32 + r) * HIDDEN;
        unsigned char* pH = dynsm + OFF_WH + r * KROWB + kq * 8;
        unsigned char* pL = dynsm + OFF_WL + r * KROWB + kq * 8;
#pragma unroll 8
        for (int i = 0; i < 32; ++i) {
            float4 v = __ldg((const float4*)(wr + kq * 4 + i * 32));
            uint2 h, lo;
            cvt4(v, h, lo);
            *(uint2*)(pH + i * 64) = h;
            *(uint2*)(pL + i * 64) = lo;
        }
    }
    __syncthreads();

    // ---- preload B fragments (W) into registers: warp w = K slice w*128 ----
    const int rowB = (l & 7) + ((l >= 16) ? 8 : 0);
    const int kBy = ((l & 8) ? 16 : 0);
    unsigned bfh[16][4], bfl[16][4];
#pragma unroll
    for (int kk = 0; kk < 8; ++kk) {
#pragma unroll
        for (int g = 0; g < 2; ++g) {
            const uint32_t o = (g * 16 + rowB) * KROWB + w * 256 + kk * 32 + kBy;
            LDSM_X4(bfh[kk * 2 + g], sbase + OFF_WH + o);
            LDSM_X4(bfl[kk * 2 + g], sbase + OFF_WL + o);
        }
    }

    // ---- A-frag lane addresses (XOR-16B swizzle on row bit3) ----
    const int rowA = (l & 7) + (l & 8);
    const int kAy = (l >> 4) * 16;
    const uint32_t aAH = sbase + OFF_AH + rowA * KROWB
                       + (kAy ^ ((rowA & 8) << 1)) + w * 256;
    const uint32_t aAL = aAH + (OFF_AL - OFF_AH);

    // ---- staging ids ----
    const int sb_ = tid >> 4, skq = tid & 15;
    const int sgoff = (bt * 16 + sb_) * HIDDEN;
    const uint32_t sAH = OFF_AH + sb_ * KROWB + ((skq * 8) ^ ((sb_ & 8) << 1));
    const uint32_t sAL = sAH + (OFF_AL - OFF_AH);

    // ---- reduce ids ----
    const int jj = tid & 31, brow = tid >> 5;

    unsigned expected = 0;
    int cur = 0;
    float lastv0 = 0.f, lastv1 = 0.f;

    for (int t = 0; t < SRC_LEN; ++t) {
        const size_t xb = (size_t)t * (BATCH * HIDDEN) + jt * 32 + jj;
        const float xv0 = __ldcg(g_xproj + xb + (size_t)(bt * 16 + brow) * HIDDEN);
        const float xv1 = __ldcg(g_xproj + xb + (size_t)(bt * 16 + brow + 8) * HIDDEN);

        // ---- stage h slice -> bf16 split SMEM ----
        const float* gh = g_h[cur] + sgoff;
#pragma unroll
        for (int i = 0; i < 16; ++i) {
            float4 v = __ldcg((const float4*)(gh + skq * 4 + i * 64));
            uint2 h, lo;
            cvt4(v, h, lo);
            *(uint2*)(dynsm + sAH + i * 128) = h;
            *(uint2*)(dynsm + sAL + i * 128) = lo;
        }
        __syncthreads();

        // ---- MMA: 8 k16 x (4 n-tiles x 3 products) ----
        float acc[4][4];
#pragma unroll
        for (int n = 0; n < 4; ++n) { acc[n][0]=0.f; acc[n][1]=0.f; acc[n][2]=0.f; acc[n][3]=0.f; }
#pragma unroll
        for (int kk = 0; kk < 8; ++kk) {
            unsigned ah[4], al[4];
            LDSM_X4(ah, aAH + kk * 32);
            LDSM_X4(al, aAL + kk * 32);
#pragma unroll
            for (int g = 0; g < 2; ++g) {
                const int ix = kk * 2 + g;
                mma16816(acc[2*g],   ah, bfh[ix][0], bfh[ix][1]);
                mma16816(acc[2*g+1], ah, bfh[ix][2], bfh[ix][3]);
                mma16816(acc[2*g],   ah, bfl[ix][0], bfl[ix][1]);
                mma16816(acc[2*g+1], ah, bfl[ix][2], bfl[ix][3]);
                mma16816(acc[2*g],   al, bfh[ix][0], bfh[ix][1]);
                mma16816(acc[2*g+1], al, bfh[ix][2], bfh[ix][3]);
            }
        }

        // ---- spill partials: red[w][r][c], row stride 40 floats ----
        {
            const int r0 = l >> 2;
            float* rp = red + (w * 16 + r0) * 40;
#pragma unroll
            for (int nt = 0; nt < 4; ++nt) {
                const int c = nt * 8 + (l & 3) * 2;
                *(float2*)(rp + c)          = make_float2(acc[nt][0], acc[nt][1]);
                *(float2*)(rp + 8 * 40 + c) = make_float2(acc[nt][2], acc[nt][3]);
            }
        }
        __syncthreads();

        // ---- reduce 8 warps, + xv, tanh, store h_next [b][k] ----
        {
            float s0 = xv0, s1 = xv1;
#pragma unroll
            for (int wq = 0; wq < 8; ++wq) {
                s0 += red[(wq * 16 + brow) * 40 + jj];
                s1 += red[(wq * 16 + brow + 8) * 40 + jj];
            }
            lastv0 = tanhf(s0);
            lastv1 = tanhf(s1);
            float* hn = g_h[cur ^ 1];
            __stcg(hn + (size_t)(bt * 16 + brow)     * HIDDEN + jt * 32 + jj, lastv0);
            __stcg(hn + (size_t)(bt * 16 + brow + 8) * HIDDEN + jt * 32 + jj, lastv1);
        }

        // ---- grid-wide barrier (monotonic counter, reset per launch) ----
        expected += NBLK;
        __threadfence();
        __syncthreads();
        if (tid == 0) {
            atomicAdd(&g_bar, 1u);
            while (*(volatile unsigned*)&g_bar < expected) { }
        }
        __syncthreads();
        cur ^= 1;
    }
    out[(size_t)(bt * 16 + brow)     * HIDDEN + jt * 32 + jj] = lastv0;
    out[(size_t)(bt * 16 + brow + 8) * HIDDEN + jt * 32 + jj] = lastv1;
}

// ---------------------------------------------------------------------------
extern "C" void kernel_launch(void* const* d_in, const int* in_sizes, int n_in,
                              void* d_out, int out_size)
{
    const int*   src = (const int*)  d_in[0];
    const float* emb = (const float*)d_in[1];
    const float* Wxh = (const float*)d_in[2];
    const float* bxh = (const float*)d_in[3];
    const float* Whh = (const float*)d_in[4];
    float* out = (float*)d_out;

    static int attr_set = 0;
    if (!attr_set) {
        cudaFuncSetAttribute(rnn_scan_kernel,
                             cudaFuncAttributeMaxDynamicSharedMemorySize, SCAN_SMEM);
        attr_set = 1;
    }

    init_kernel<<<256, 256>>>();
    probe_kernel<<<1, 32>>>();       // ncu alignment: capture -> rnn_scan_kernel
    xproj_kernel<<<dim3(8, 256), 256>>>(src, emb, Wxh, bxh);
    rnn_scan_kernel<<<NBLK, 256, SCAN_SMEM>>>(Whh, out);
}